// round 2
// baseline (speedup 1.0000x reference)
#include <cuda_runtime.h>

#define TW 32
#define TH 16
#define ICH 32
#define OCH 32
#define HH 512
#define WW 512

// ---- packed f32x2 helpers (Blackwell sm_103a) ----
__device__ __forceinline__ unsigned long long pk2(float lo, float hi) {
    unsigned long long r;
    asm("mov.b64 %0, {%1,%2};" : "=l"(r) : "f"(lo), "f"(hi));
    return r;
}
__device__ __forceinline__ void fma2(unsigned long long& d, unsigned long long a, unsigned long long b) {
    asm("fma.rn.f32x2 %0, %1, %2, %0;" : "+l"(d) : "l"(a), "l"(b));
}

// smem layout: [0, 73728)  packed weights  wp_s[(ic*9 + r*3 + s)*32 + oc] as (w,w) u64
//              [73728, ..) input tile      in_s[(ic*18 + row)*36 + col]   (rows 0..17, cols 0..33)
#define SMEM_W_ULL 9216
#define SMEM_BYTES (SMEM_W_ULL * 8 + ICH * 18 * 36 * 4)

__global__ void __launch_bounds__(256) conv3x3_kernel(
    const float* __restrict__ x,
    const float* __restrict__ w,
    const float* __restrict__ bias,
    float* __restrict__ out)
{
    extern __shared__ unsigned char smem[];
    unsigned long long* wp_s = (unsigned long long*)smem;
    float* in_s = (float*)(smem + SMEM_W_ULL * 8);

    const int tid  = threadIdx.x;
    const int n    = blockIdx.z;
    const int row0 = blockIdx.y * TH;
    const int col0 = blockIdx.x * TW;

    // ---- load weights, replicated into packed pairs ----
    for (int e = tid; e < SMEM_W_ULL; e += 256) {
        int oc = e & 31;
        int q  = e >> 5;         // ic*9 + rs
        int rs = q % 9;
        int ic = q / 9;
        float wv = w[(oc * ICH + ic) * 9 + rs];
        wp_s[e] = pk2(wv, wv);
    }

    // ---- load input tile with halo (zero padding at borders) ----
    const float* xin = x + (size_t)n * ICH * HH * WW;
    for (int e = tid; e < ICH * 18 * 34; e += 256) {
        int col = e % 34;
        int t   = e / 34;
        int row = t % 18;
        int ic  = t / 18;
        int gy = row0 + row - 1;
        int gx = col0 + col - 1;
        float v = 0.0f;
        if ((unsigned)gy < (unsigned)HH && (unsigned)gx < (unsigned)WW)
            v = xin[(ic * HH + gy) * WW + gx];
        in_s[(ic * 18 + row) * 36 + col] = v;
    }
    __syncthreads();

    // ---- per-thread work assignment: 8 oc x (1 row x 8 cols) ----
    const int ocb  = (tid >> 6) * 8;     // 0,8,16,24
    const int pg   = tid & 63;
    const int orow = pg >> 2;            // 0..15
    const int cb   = (pg & 3) * 8;       // 0,8,16,24

    unsigned long long acc[8][4];
    #pragma unroll
    for (int i = 0; i < 8; i++) {
        float b = __ldg(&bias[ocb + i]);
        unsigned long long bb = pk2(b, b);
        #pragma unroll
        for (int j = 0; j < 4; j++) acc[i][j] = bb;
    }

    for (int ic = 0; ic < ICH; ic++) {
        #pragma unroll
        for (int r = 0; r < 3; r++) {
            const float* xrow = &in_s[(ic * 18 + orow + r) * 36 + cb];
            float4 xa = *(const float4*)(xrow);
            float4 xb = *(const float4*)(xrow + 4);
            float4 xc = *(const float4*)(xrow + 8);   // only .x,.y used

            // even-aligned pixel pairs (s=0 and s=2)
            unsigned long long p0 = pk2(xa.x, xa.y);
            unsigned long long p1 = pk2(xa.z, xa.w);
            unsigned long long p2 = pk2(xb.x, xb.y);
            unsigned long long p3 = pk2(xb.z, xb.w);
            unsigned long long p4 = pk2(xc.x, xc.y);
            // odd pairs (s=1)
            unsigned long long q0 = pk2(xa.y, xa.z);
            unsigned long long q1 = pk2(xa.w, xb.x);
            unsigned long long q2 = pk2(xb.y, xb.z);
            unsigned long long q3 = pk2(xb.w, xc.x);

            const unsigned long long* wrow = &wp_s[(ic * 9 + r * 3) * 32 + ocb];
            const ulonglong2* wr0 = (const ulonglong2*)(wrow);
            const ulonglong2* wr1 = (const ulonglong2*)(wrow + 32);
            const ulonglong2* wr2 = (const ulonglong2*)(wrow + 64);

            // s = 0: pixels j+0 -> pairs p0..p3
            #pragma unroll
            for (int i2 = 0; i2 < 4; i2++) {
                ulonglong2 wv = wr0[i2];
                fma2(acc[2*i2+0][0], wv.x, p0);
                fma2(acc[2*i2+0][1], wv.x, p1);
                fma2(acc[2*i2+0][2], wv.x, p2);
                fma2(acc[2*i2+0][3], wv.x, p3);
                fma2(acc[2*i2+1][0], wv.y, p0);
                fma2(acc[2*i2+1][1], wv.y, p1);
                fma2(acc[2*i2+1][2], wv.y, p2);
                fma2(acc[2*i2+1][3], wv.y, p3);
            }
            // s = 1: pixels j+1 -> pairs q0..q3
            #pragma unroll
            for (int i2 = 0; i2 < 4; i2++) {
                ulonglong2 wv = wr1[i2];
                fma2(acc[2*i2+0][0], wv.x, q0);
                fma2(acc[2*i2+0][1], wv.x, q1);
                fma2(acc[2*i2+0][2], wv.x, q2);
                fma2(acc[2*i2+0][3], wv.x, q3);
                fma2(acc[2*i2+1][0], wv.y, q0);
                fma2(acc[2*i2+1][1], wv.y, q1);
                fma2(acc[2*i2+1][2], wv.y, q2);
                fma2(acc[2*i2+1][3], wv.y, q3);
            }
            // s = 2: pixels j+2 -> pairs p1..p4
            #pragma unroll
            for (int i2 = 0; i2 < 4; i2++) {
                ulonglong2 wv = wr2[i2];
                fma2(acc[2*i2+0][0], wv.x, p1);
                fma2(acc[2*i2+0][1], wv.x, p2);
                fma2(acc[2*i2+0][2], wv.x, p3);
                fma2(acc[2*i2+0][3], wv.x, p4);
                fma2(acc[2*i2+1][0], wv.y, p1);
                fma2(acc[2*i2+1][1], wv.y, p2);
                fma2(acc[2*i2+1][2], wv.y, p3);
                fma2(acc[2*i2+1][3], wv.y, p4);
            }
        }
    }

    // ---- store: 8 oc planes, 8 contiguous cols each (2x 16B stores) ----
    const int gy = row0 + orow;
    float* op = out + (((size_t)n * OCH + ocb) * HH + gy) * WW + col0 + cb;
    #pragma unroll
    for (int i = 0; i < 8; i++) {
        ulonglong2 v0 = make_ulonglong2(acc[i][0], acc[i][1]);
        ulonglong2 v1 = make_ulonglong2(acc[i][2], acc[i][3]);
        *(ulonglong2*)(op)     = v0;
        *(ulonglong2*)(op + 4) = v1;
        op += (size_t)HH * WW;
    }
}

extern "C" void kernel_launch(void* const* d_in, const int* in_sizes, int n_in,
                              void* d_out, int out_size) {
    const float* x    = (const float*)d_in[0];
    const float* w    = (const float*)d_in[1];
    const float* bias = (const float*)d_in[2];
    float* out        = (float*)d_out;

    cudaFuncSetAttribute(conv3x3_kernel,
                         cudaFuncAttributeMaxDynamicSharedMemorySize, SMEM_BYTES);

    dim3 grid(WW / TW, HH / TH, 8);   // 16 x 32 x 8 = 4096 CTAs
    conv3x3_kernel<<<grid, 256, SMEM_BYTES>>>(x, w, bias, out);
}

// round 3
// speedup vs baseline: 1.3113x; 1.3113x over previous
#include <cuda_runtime.h>

#define ICH 32
#define OCH 32
#define HH 512
#define WW 512
#define TW 32
#define TH 16

// ---- packed f32x2 helpers (Blackwell sm_103a) ----
__device__ __forceinline__ unsigned long long pk2(float lo, float hi) {
    unsigned long long r;
    asm("mov.b64 %0, {%1,%2};" : "=l"(r) : "f"(lo), "f"(hi));
    return r;
}
__device__ __forceinline__ void fma2(unsigned long long& d, unsigned long long a, unsigned long long b) {
    asm("fma.rn.f32x2 %0, %1, %2, %0;" : "+l"(d) : "l"(a), "l"(b));
}

// Duplicated weights in global: wdup[((oh*ICH + ic)*9 + r*3 + s)*16 + ocl] = (w,w)
// oh = oc half (0/1), ocl = oc within half (0..15).  2*32*9*16 = 9216 u64 = 72KB.
__device__ unsigned long long wdup_g[2 * ICH * 9 * 16];

__global__ void repack_weights(const float* __restrict__ w) {
    int idx = blockIdx.x * blockDim.x + threadIdx.x;
    if (idx >= 2 * ICH * 9 * 16) return;
    int ocl = idx & 15;
    int t   = idx >> 4;
    int rs  = t % 9;
    int ic  = (t / 9) & 31;
    int oh  = t / (9 * ICH);
    int ocg = oh * 16 + ocl;
    float v = w[(ocg * ICH + ic) * 9 + rs];
    wdup_g[idx] = pk2(v, v);
}

// Input tile smem: in_s[(ic*18 + row)*36 + col], rows 0..17 (halo), cols 0..33 used.
#define SMEM_BYTES (ICH * 18 * 36 * 4)

__global__ void __launch_bounds__(256, 2) conv3x3_kernel(
    const float* __restrict__ x,
    const float* __restrict__ bias,
    float* __restrict__ out)
{
    extern __shared__ float in_s[];

    const int tid   = threadIdx.x;
    const int nz    = blockIdx.z;        // n*2 + ohalf
    const int n     = nz >> 1;
    const int oh    = nz & 1;
    const int row0  = blockIdx.y * TH;
    const int col0  = blockIdx.x * TW;

    // ---- load input tile with halo (zero padded) ----
    const float* xin = x + (size_t)n * ICH * HH * WW;
    for (int e = tid; e < ICH * 18 * 34; e += 256) {
        int col = e % 34;
        int t   = e / 34;
        int row = t % 18;
        int ic  = t / 18;
        int gy = row0 + row - 1;
        int gx = col0 + col - 1;
        float v = 0.0f;
        if ((unsigned)gy < (unsigned)HH && (unsigned)gx < (unsigned)WW)
            v = xin[(ic * HH + gy) * WW + gx];
        in_s[(ic * 18 + row) * 36 + col] = v;
    }
    __syncthreads();

    // ---- per-thread: 4 oc x 8 cols (4 pixel pairs) ----
    const int ocg  = tid >> 6;           // 0..3  -> local oc base ocg*4
    const int pg   = tid & 63;
    const int orow = pg >> 2;            // 0..15
    const int cb   = (pg & 3) * 8;       // 0,8,16,24

    unsigned long long acc[4][4];
    #pragma unroll
    for (int i = 0; i < 4; i++) {
        float b = __ldg(&bias[oh * 16 + ocg * 4 + i]);
        unsigned long long bb = pk2(b, b);
        #pragma unroll
        for (int j = 0; j < 4; j++) acc[i][j] = bb;
    }

    const unsigned long long* wbase0 = &wdup_g[((size_t)oh * ICH * 9) * 16 + ocg * 4];

    for (int ic = 0; ic < ICH; ic++) {
        #pragma unroll
        for (int r = 0; r < 3; r++) {
            const float* xrow = &in_s[(ic * 18 + orow + r) * 36 + cb];
            float4 xa = *(const float4*)(xrow);
            float4 xb = *(const float4*)(xrow + 4);
            float2 xc = *(const float2*)(xrow + 8);

            unsigned long long p0 = pk2(xa.x, xa.y);
            unsigned long long p1 = pk2(xa.z, xa.w);
            unsigned long long p2 = pk2(xb.x, xb.y);
            unsigned long long p3 = pk2(xb.z, xb.w);
            unsigned long long p4 = pk2(xc.x, xc.y);
            unsigned long long q0 = pk2(xa.y, xa.z);
            unsigned long long q1 = pk2(xa.w, xb.x);
            unsigned long long q2 = pk2(xb.y, xb.z);
            unsigned long long q3 = pk2(xb.w, xc.x);

            const unsigned long long* wr = wbase0 + (size_t)(ic * 9 + r * 3) * 16;
            const ulonglong2* w0 = (const ulonglong2*)(wr);
            const ulonglong2* w1 = (const ulonglong2*)(wr + 16);
            const ulonglong2* w2 = (const ulonglong2*)(wr + 32);

            // s = 0: pairs p0..p3
            #pragma unroll
            for (int i2 = 0; i2 < 2; i2++) {
                ulonglong2 wv = __ldg(&w0[i2]);
                fma2(acc[2*i2+0][0], wv.x, p0);
                fma2(acc[2*i2+0][1], wv.x, p1);
                fma2(acc[2*i2+0][2], wv.x, p2);
                fma2(acc[2*i2+0][3], wv.x, p3);
                fma2(acc[2*i2+1][0], wv.y, p0);
                fma2(acc[2*i2+1][1], wv.y, p1);
                fma2(acc[2*i2+1][2], wv.y, p2);
                fma2(acc[2*i2+1][3], wv.y, p3);
            }
            // s = 1: pairs q0..q3
            #pragma unroll
            for (int i2 = 0; i2 < 2; i2++) {
                ulonglong2 wv = __ldg(&w1[i2]);
                fma2(acc[2*i2+0][0], wv.x, q0);
                fma2(acc[2*i2+0][1], wv.x, q1);
                fma2(acc[2*i2+0][2], wv.x, q2);
                fma2(acc[2*i2+0][3], wv.x, q3);
                fma2(acc[2*i2+1][0], wv.y, q0);
                fma2(acc[2*i2+1][1], wv.y, q1);
                fma2(acc[2*i2+1][2], wv.y, q2);
                fma2(acc[2*i2+1][3], wv.y, q3);
            }
            // s = 2: pairs p1..p4
            #pragma unroll
            for (int i2 = 0; i2 < 2; i2++) {
                ulonglong2 wv = __ldg(&w2[i2]);
                fma2(acc[2*i2+0][0], wv.x, p1);
                fma2(acc[2*i2+0][1], wv.x, p2);
                fma2(acc[2*i2+0][2], wv.x, p3);
                fma2(acc[2*i2+0][3], wv.x, p4);
                fma2(acc[2*i2+1][0], wv.y, p1);
                fma2(acc[2*i2+1][1], wv.y, p2);
                fma2(acc[2*i2+1][2], wv.y, p3);
                fma2(acc[2*i2+1][3], wv.y, p4);
            }
        }
    }

    // ---- store: 4 oc planes, 8 contiguous cols each (2x 16B stores) ----
    const int gy = row0 + orow;
    float* op = out + (((size_t)n * OCH + oh * 16 + ocg * 4) * HH + gy) * WW + col0 + cb;
    #pragma unroll
    for (int i = 0; i < 4; i++) {
        *(ulonglong2*)(op)     = make_ulonglong2(acc[i][0], acc[i][1]);
        *(ulonglong2*)(op + 4) = make_ulonglong2(acc[i][2], acc[i][3]);
        op += (size_t)HH * WW;
    }
}

extern "C" void kernel_launch(void* const* d_in, const int* in_sizes, int n_in,
                              void* d_out, int out_size) {
    const float* x    = (const float*)d_in[0];
    const float* w    = (const float*)d_in[1];
    const float* bias = (const float*)d_in[2];
    float* out        = (float*)d_out;

    repack_weights<<<(2 * ICH * 9 * 16 + 255) / 256, 256>>>(w);

    cudaFuncSetAttribute(conv3x3_kernel,
                         cudaFuncAttributeMaxDynamicSharedMemorySize, SMEM_BYTES);

    dim3 grid(WW / TW, HH / TH, 8 * 2);  // 16 x 32 x 16 = 8192 CTAs
    conv3x3_kernel<<<grid, 256, SMEM_BYTES>>>(x, bias, out);
}